// round 8
// baseline (speedup 1.0000x reference)
#include <cuda_runtime.h>
#include <cuda_bf16.h>
#include <cstdint>

#define NCH 128
#define HEADS 4
#define NMAX 50000
#define EMAX 600000
#define TOTMAX (EMAX + NMAX)
#define BN_EPS 1e-5f
#define NLAYERS 6

// ---------------- device scratch (no allocs allowed) ----------------
__device__ float g_H[NMAX * NCH];     // per-layer GEMM output (gather source)
__device__ float g_B[NMAX * NCH];     // stored activation (residual identity)
__device__ float g_AGG[NMAX * NCH];   // pre-BN aggregation output
__device__ float g_AS[NMAX * HEADS];
__device__ float g_AD[NMAX * HEADS];
__device__ int   g_deg[NMAX];         // .bss zero; re-zeroed by k_scatter each run
__device__ int   g_rowptr[NMAX + 1];
__device__ int   g_cursor[NMAX];
__device__ int   g_csrsrc[TOTMAX];
__device__ float g_bnsum[NCH];        // .bss zero; reset by agg finalizer
__device__ float g_bnsq[NCH];
__device__ float g_scale[NCH];
__device__ float g_shift[NCH];
__device__ int   g_ctr;               // .bss zero; reset by agg finalizer

__device__ __forceinline__ float lrelu(float x) { return x >= 0.f ? x : 0.2f * x; }

__device__ __forceinline__ uint32_t smem_u32(const void* p) {
    uint32_t a;
    asm("{ .reg .u64 t; cvta.to.shared.u64 t, %1; cvt.u32.u64 %0, t; }" : "=r"(a) : "l"(p));
    return a;
}
__device__ __forceinline__ void ldm_x4(uint32_t& r0, uint32_t& r1, uint32_t& r2, uint32_t& r3,
                                       uint32_t addr) {
    asm volatile("ldmatrix.sync.aligned.m8n8.x4.shared.b16 {%0,%1,%2,%3}, [%4];"
        : "=r"(r0), "=r"(r1), "=r"(r2), "=r"(r3) : "r"(addr));
}
__device__ __forceinline__ void ldm_x4t(uint32_t& r0, uint32_t& r1, uint32_t& r2, uint32_t& r3,
                                        uint32_t addr) {
    asm volatile("ldmatrix.sync.aligned.m8n8.x4.trans.shared.b16 {%0,%1,%2,%3}, [%4];"
        : "=r"(r0), "=r"(r1), "=r"(r2), "=r"(r3) : "r"(addr));
}
__device__ __forceinline__ void mma_bf16(float* d, const uint32_t* a, const uint32_t* b) {
    asm volatile("mma.sync.aligned.m16n8k16.row.col.f32.bf16.bf16.f32 "
        "{%0,%1,%2,%3}, {%4,%5,%6,%7}, {%8,%9}, {%0,%1,%2,%3};"
        : "+f"(d[0]), "+f"(d[1]), "+f"(d[2]), "+f"(d[3])
        : "r"(a[0]), "r"(a[1]), "r"(a[2]), "r"(a[3]), "r"(b[0]), "r"(b[1]));
}

// ---------------- CSR build (deg+1 folded into scan; deg re-zeroed in scatter) ----------------
__global__ void k_hist(const int* __restrict__ ei, int E) {
    int i = blockIdx.x * blockDim.x + threadIdx.x;
    if (i < E) atomicAdd(&g_deg[ei[E + i]], 1);
}

__global__ void k_scan(int N) {
    __shared__ int ssum[1024];
    int t = threadIdx.x;
    int per = (N + 1023) / 1024;
    int beg = t * per;
    int end = min(beg + per, N);
    if (beg > N) beg = N;
    int local = 0;
    for (int i = beg; i < end; i++) local += g_deg[i] + 1;   // +1 self-loop
    ssum[t] = local;
    __syncthreads();
    for (int off = 1; off < 1024; off <<= 1) {
        int add = (t >= off) ? ssum[t - off] : 0;
        __syncthreads();
        ssum[t] += add;
        __syncthreads();
    }
    int run = ssum[t] - local;
    for (int i = beg; i < end; i++) {
        g_rowptr[i] = run;
        g_cursor[i] = run;
        run += g_deg[i] + 1;
    }
    if (t == 1023) g_rowptr[N] = run;
}

__global__ void k_scatter(const int* __restrict__ ei, int E, int N) {
    int i = blockIdx.x * blockDim.x + threadIdx.x;
    if (i < E) {
        int d = ei[E + i];
        int pos = atomicAdd(&g_cursor[d], 1);
        g_csrsrc[pos] = ei[i];
    } else if (i < E + N) {
        int n = i - E;
        int pos = atomicAdd(&g_cursor[n], 1);
        g_csrsrc[pos] = n;
        g_deg[n] = 0;   // reset histogram for next replay (scan already consumed it)
    }
}

// ---------------- GEMM via mma.sync: H = act(X) @ W + att logits ----------------
// 64x128 tile per block, 256 threads (8 warps, 4x2 of 16x64 warp tiles), occ 2.
// 3-pass bf16 split precision (Ahi*Bhi + Ahi*Blo + Alo*Bhi), fp32 accumulate.
// W kept in native [k][n] layout; B fragments loaded with ldmatrix.trans.
// Load phase fuses BN(scale/shift) + residual + ReLU + act store + hi/lo split.
#define LDA 136                      // bf16 elems per smem row (128 + 8 pad)
#define SM_AHI 0
#define SM_ALO (SM_AHI + 64 * LDA * 2)
#define SM_WHI (SM_ALO + 64 * LDA * 2)
#define SM_WLO (SM_WHI + 128 * LDA * 2)
#define SM_ATT (SM_WLO + 128 * LDA * 2)
#define GEMM_SMEM (SM_ATT + 1024)
#define SM_D SM_AHI                  // D overlay after MMA: [64][132] f32 = 33.8KB
#define LDD 132

__global__ void __launch_bounds__(256, 2)
k_gemm_mma(const float* __restrict__ Xraw,   // non-null for layer 0 only
           const float* __restrict__ res,    // optional residual (pre-activation add)
           float* __restrict__ act,          // optional activation store
           const float* __restrict__ Wl,     // layer weight [k][n] fp32
           const float* __restrict__ atts, const float* __restrict__ attd, int N) {
    extern __shared__ char sm[];
    uint32_t smb = smem_u32(sm);
    const int t = threadIdx.x;

    float* sAtt = (float*)(sm + SM_ATT);
    if (t < 128) { sAtt[t] = atts[t]; sAtt[128 + t] = attd[t]; }

    const int row0 = blockIdx.x * 64;

    // --- X: load + (optional) BN/res/ReLU + bf16 hi/lo split ---
    for (int i = t; i < 2048; i += 256) {   // 64 rows x 32 float4
        int r = i >> 5, c4 = (i & 31) * 4;
        int gr = row0 + r;
        float4 v = make_float4(0.f, 0.f, 0.f, 0.f);
        if (gr < N) {
            if (Xraw) {
                v = *(const float4*)&Xraw[gr * NCH + c4];
            } else {
                v = *(const float4*)&g_AGG[gr * NCH + c4];
                float4 sc = *(const float4*)&g_scale[c4];
                float4 sh = *(const float4*)&g_shift[c4];
                v.x = fmaf(v.x, sc.x, sh.x); v.y = fmaf(v.y, sc.y, sh.y);
                v.z = fmaf(v.z, sc.z, sh.z); v.w = fmaf(v.w, sc.w, sh.w);
                if (res) {
                    float4 rr = *(const float4*)&res[gr * NCH + c4];
                    v.x += rr.x; v.y += rr.y; v.z += rr.z; v.w += rr.w;
                }
                v.x = fmaxf(v.x, 0.f); v.y = fmaxf(v.y, 0.f);
                v.z = fmaxf(v.z, 0.f); v.w = fmaxf(v.w, 0.f);
                if (act) *(float4*)&act[gr * NCH + c4] = v;
            }
        }
        __nv_bfloat16 h0 = __float2bfloat16_rn(v.x), h1 = __float2bfloat16_rn(v.y);
        __nv_bfloat16 h2 = __float2bfloat16_rn(v.z), h3 = __float2bfloat16_rn(v.w);
        __nv_bfloat16 l0 = __float2bfloat16_rn(v.x - __bfloat162float(h0));
        __nv_bfloat16 l1 = __float2bfloat16_rn(v.y - __bfloat162float(h1));
        __nv_bfloat16 l2 = __float2bfloat16_rn(v.z - __bfloat162float(h2));
        __nv_bfloat16 l3 = __float2bfloat16_rn(v.w - __bfloat162float(h3));
        uint2 hv, lv;
        hv.x = ((uint32_t)__bfloat16_as_ushort(h1) << 16) | __bfloat16_as_ushort(h0);
        hv.y = ((uint32_t)__bfloat16_as_ushort(h3) << 16) | __bfloat16_as_ushort(h2);
        lv.x = ((uint32_t)__bfloat16_as_ushort(l1) << 16) | __bfloat16_as_ushort(l0);
        lv.y = ((uint32_t)__bfloat16_as_ushort(l3) << 16) | __bfloat16_as_ushort(l2);
        *(uint2*)(sm + SM_AHI + (r * LDA + c4) * 2) = hv;
        *(uint2*)(sm + SM_ALO + (r * LDA + c4) * 2) = lv;
    }
    // --- W: load fp32 [k][n], split hi/lo inline, keep native layout ---
    for (int i = t; i < 4096; i += 256) {   // 128 rows x 32 float4
        int k = i >> 5, n4 = (i & 31) * 4;
        float4 wv = *(const float4*)&Wl[k * NCH + n4];
        __nv_bfloat16 h0 = __float2bfloat16_rn(wv.x), h1 = __float2bfloat16_rn(wv.y);
        __nv_bfloat16 h2 = __float2bfloat16_rn(wv.z), h3 = __float2bfloat16_rn(wv.w);
        __nv_bfloat16 l0 = __float2bfloat16_rn(wv.x - __bfloat162float(h0));
        __nv_bfloat16 l1 = __float2bfloat16_rn(wv.y - __bfloat162float(h1));
        __nv_bfloat16 l2 = __float2bfloat16_rn(wv.z - __bfloat162float(h2));
        __nv_bfloat16 l3 = __float2bfloat16_rn(wv.w - __bfloat162float(h3));
        uint2 hv, lv;
        hv.x = ((uint32_t)__bfloat16_as_ushort(h1) << 16) | __bfloat16_as_ushort(h0);
        hv.y = ((uint32_t)__bfloat16_as_ushort(h3) << 16) | __bfloat16_as_ushort(h2);
        lv.x = ((uint32_t)__bfloat16_as_ushort(l1) << 16) | __bfloat16_as_ushort(l0);
        lv.y = ((uint32_t)__bfloat16_as_ushort(l3) << 16) | __bfloat16_as_ushort(l2);
        *(uint2*)(sm + SM_WHI + (k * LDA + n4) * 2) = hv;
        *(uint2*)(sm + SM_WLO + (k * LDA + n4) * 2) = lv;
    }
    __syncthreads();

    // --- 3-pass HMMA main loop ---
    const int w = t >> 5, l = t & 31;
    const int wm = (w & 3) * 16, wn = (w >> 2) * 64;
    float d[8][4];
#pragma unroll
    for (int nt = 0; nt < 8; nt++)
#pragma unroll
        for (int q = 0; q < 4; q++) d[nt][q] = 0.f;

    const int a_row = l & 15, a_koff = (l >> 4) * 8;
    // B (trans) lane addressing: matrix = l/8: {k0-7@n0, k8-15@n0, k0-7@n0+8, k8-15@n0+8}
    const int b_krow = (l & 7) + ((l >> 3) & 1) * 8;
    const int b_noff = (l >> 4) * 8;

#pragma unroll
    for (int pass = 0; pass < 3; pass++) {
        uint32_t Abase = smb + ((pass == 2) ? SM_ALO : SM_AHI);
        uint32_t Bbase = smb + ((pass == 1) ? SM_WLO : SM_WHI);
        uint32_t aAddr = Abase + ((wm + a_row) * LDA + a_koff) * 2;

#pragma unroll
        for (int ks = 0; ks < 8; ks++) {
            uint32_t a0[4];
            ldm_x4(a0[0], a0[1], a0[2], a0[3], aAddr + ks * 32);
            uint32_t b[8][2];
#pragma unroll
            for (int g = 0; g < 4; g++) {
                uint32_t r0, r1, r2, r3;
                uint32_t bAddr = Bbase +
                    ((ks * 16 + b_krow) * LDA + wn + g * 16 + b_noff) * 2;
                ldm_x4t(r0, r1, r2, r3, bAddr);
                b[g * 2][0] = r0;     b[g * 2][1] = r1;
                b[g * 2 + 1][0] = r2; b[g * 2 + 1][1] = r3;
            }
#pragma unroll
            for (int nt = 0; nt < 8; nt++) mma_bf16(d[nt], a0, b[nt]);
        }
    }
    __syncthreads();   // ldmatrix done; safe to overlay D on A region

    // --- stage D to smem ---
    float* sD = (float*)(sm + SM_D);
#pragma unroll
    for (int nt = 0; nt < 8; nt++) {
        int r = wm + (l >> 2);
        int c = wn + nt * 8 + (l & 3) * 2;
        *(float2*)&sD[r * LDD + c]       = make_float2(d[nt][0], d[nt][1]);
        *(float2*)&sD[(r + 8) * LDD + c] = make_float2(d[nt][2], d[nt][3]);
    }
    __syncthreads();

    // --- readout: thread owns a 32-col head chunk of one row ---
    {
        int r = t >> 2, hq = t & 3, cb0 = hq * 32;
        int gr = row0 + r;
        if (gr < N) {
            float ps = 0.f, pd = 0.f;
#pragma unroll
            for (int c = 0; c < 32; c += 4) {
                float4 v = *(float4*)&sD[r * LDD + cb0 + c];
                *(float4*)&g_H[gr * NCH + cb0 + c] = v;
                const float* aS = &sAtt[cb0 + c];
                const float* aD = &sAtt[128 + cb0 + c];
                ps += fmaf(v.x, aS[0], fmaf(v.y, aS[1], fmaf(v.z, aS[2], v.w * aS[3])));
                pd += fmaf(v.x, aD[0], fmaf(v.y, aD[1], fmaf(v.z, aD[2], v.w * aD[3])));
            }
            g_AS[gr * 4 + hq] = ps;
            g_AD[gr * 4 + hq] = pd;
        }
    }
}

// ---------------- aggregation: warp/node, one-pass online softmax (8-wide) + BN finalize ----------------
__global__ void __launch_bounds__(256)
k_agg(const float* __restrict__ bias, const float* __restrict__ gamma,
      const float* __restrict__ beta, int N) {
    __shared__ float sSum[128], sSq[128];
    __shared__ int isLast;
    int t = threadIdx.x;
    if (t < 128) { sSum[t] = 0.f; sSq[t] = 0.f; }
    __syncthreads();

    int node = (blockIdx.x * 256 + t) >> 5;
    int lane = t & 31;
    if (node < N) {
        int beg = g_rowptr[node], end = g_rowptr[node + 1];
        int hd = lane >> 3;
        int cb = lane * 4;
        float adv = g_AD[node * 4 + hd];
        int last = end - 1;

        float m = -1e30f, s = 0.f;
        float4 acc = make_float4(0.f, 0.f, 0.f, 0.f);
        for (int j = beg; j < end; j += 8) {
            int idx[8];
#pragma unroll
            for (int q = 0; q < 8; q++) idx[q] = g_csrsrc[min(j + q, last)];
            float lg[8];
#pragma unroll
            for (int q = 0; q < 8; q++) lg[q] = g_AS[idx[q] * 4 + hd];
            float4 h[8];
#pragma unroll
            for (int q = 0; q < 8; q++) h[q] = *(const float4*)&g_H[idx[q] * NCH + cb];
            float e[8];
#pragma unroll
            for (int q = 0; q < 8; q++)
                e[q] = (j + q < end) ? lrelu(lg[q] + adv) : -1e30f;
            float mb = m;
#pragma unroll
            for (int q = 0; q < 8; q++) mb = fmaxf(mb, e[q]);
            float rs = __expf(m - mb);
            m = mb;
            float w[8];
            float ws = 0.f;
#pragma unroll
            for (int q = 0; q < 8; q++) { w[q] = __expf(e[q] - mb); ws += w[q]; }
            s = fmaf(s, rs, ws);
            float ax = acc.x * rs, ay = acc.y * rs, az = acc.z * rs, aw = acc.w * rs;
#pragma unroll
            for (int q = 0; q < 8; q++) {
                ax = fmaf(w[q], h[q].x, ax);
                ay = fmaf(w[q], h[q].y, ay);
                az = fmaf(w[q], h[q].z, az);
                aw = fmaf(w[q], h[q].w, aw);
            }
            acc.x = ax; acc.y = ay; acc.z = az; acc.w = aw;
        }
        float inv = __fdividef(1.f, s);
        float4 b4 = *(const float4*)&bias[cb];
        acc.x = fmaf(acc.x, inv, b4.x);
        acc.y = fmaf(acc.y, inv, b4.y);
        acc.z = fmaf(acc.z, inv, b4.z);
        acc.w = fmaf(acc.w, inv, b4.w);
        *(float4*)&g_AGG[node * NCH + cb] = acc;

        atomicAdd(&sSum[cb],     acc.x); atomicAdd(&sSq[cb],     acc.x * acc.x);
        atomicAdd(&sSum[cb + 1], acc.y); atomicAdd(&sSq[cb + 1], acc.y * acc.y);
        atomicAdd(&sSum[cb + 2], acc.z); atomicAdd(&sSq[cb + 2], acc.z * acc.z);
        atomicAdd(&sSum[cb + 3], acc.w); atomicAdd(&sSq[cb + 3], acc.w * acc.w);
    }
    __syncthreads();
    if (t < 128) {
        atomicAdd(&g_bnsum[t], sSum[t]);
        atomicAdd(&g_bnsq[t],  sSq[t]);
    }
    __threadfence();
    __syncthreads();
    if (t == 0) isLast = (atomicAdd(&g_ctr, 1) == (int)gridDim.x - 1);
    __syncthreads();
    if (isLast) {
        __threadfence();
        if (t < 128) {
            float invN = 1.f / (float)N;
            float mu = g_bnsum[t] * invN;
            float var = fmaxf(g_bnsq[t] * invN - mu * mu, 0.f);
            float sc = gamma[t] * rsqrtf(var + BN_EPS);
            g_scale[t] = sc;
            g_shift[t] = beta[t] - mu * sc;
            g_bnsum[t] = 0.f;   // reset for next layer / next replay
            g_bnsq[t]  = 0.f;
        }
        if (t == 0) g_ctr = 0;
    }
}

// ---------------- final BN apply (layer 5 only) ----------------
__global__ void k_bn(const float* __restrict__ res, float* __restrict__ outp, int n4) {
    int i = blockIdx.x * blockDim.x + threadIdx.x;
    if (i >= n4) return;
    float4 v = *(const float4*)&g_AGG[i * 4];
    int c = (i * 4) & 127;
    float4 sc = *(const float4*)&g_scale[c];
    float4 sh = *(const float4*)&g_shift[c];
    v.x = fmaf(v.x, sc.x, sh.x);
    v.y = fmaf(v.y, sc.y, sh.y);
    v.z = fmaf(v.z, sc.z, sh.z);
    v.w = fmaf(v.w, sc.w, sh.w);
    if (res) {
        float4 r = *(const float4*)&res[i * 4];
        v.x += r.x; v.y += r.y; v.z += r.z; v.w += r.w;
    }
    v.x = fmaxf(v.x, 0.f); v.y = fmaxf(v.y, 0.f);
    v.z = fmaxf(v.z, 0.f); v.w = fmaxf(v.w, 0.f);
    *(float4*)&outp[i * 4] = v;
}

// ---------------- launch ----------------
extern "C" void kernel_launch(void* const* d_in, const int* in_sizes, int n_in,
                              void* d_out, int out_size) {
    const float* x      = (const float*)d_in[0];
    const int*   ei     = (const int*)d_in[1];
    const float* Ws     = (const float*)d_in[2];
    const float* atts   = (const float*)d_in[3];
    const float* attd   = (const float*)d_in[4];
    const float* biases = (const float*)d_in[5];
    const float* gammas = (const float*)d_in[6];
    const float* betas  = (const float*)d_in[7];
    float* out = (float*)d_out;

    const int N = in_sizes[0] / NCH;
    const int E = in_sizes[1] / 2;

    void* pB;
    cudaGetSymbolAddress(&pB, g_B);
    float* B = (float*)pB;

    cudaFuncSetAttribute(k_gemm_mma, cudaFuncAttributeMaxDynamicSharedMemorySize, GEMM_SMEM);

    // CSR build (deg zeroed by previous run's scatter; .bss zero on first run)
    k_hist<<<(E + 255) / 256, 256>>>(ei, E);
    k_scan<<<1, 1024>>>(N);
    k_scatter<<<(E + N + 255) / 256, 256>>>(ei, E, N);

    // per-layer GEMM load config: layer0 reads raw x; others read g_AGG+BN(prev).
    const float* xins[6] = {x, nullptr, nullptr, nullptr, nullptr, nullptr};
    const float* ress[6] = {nullptr, nullptr, nullptr, nullptr, B, nullptr};  // gemm4 adds a1
    float*       acts[6] = {nullptr, nullptr, B, nullptr, B, nullptr};        // gemm2 stores a1, gemm4 stores a3

    const int gblk = (N + 63) / 64;
    const int n4 = N * (NCH / 4);
    for (int i = 0; i < 6; i++) {
        k_gemm_mma<<<gblk, 256, GEMM_SMEM>>>(
            xins[i], ress[i], acts[i], Ws + i * NCH * NCH,
            atts + i * NCH, attd + i * NCH, N);
        k_agg<<<(N * 32 + 255) / 256, 256>>>(
            biases + i * NCH, gammas + i * NCH, betas + i * NCH, N);
    }
    // final: out = relu(bn5(AGG5) + a3)
    k_bn<<<(n4 + 255) / 256, 256>>>(B, out, n4);
}